// round 5
// baseline (speedup 1.0000x reference)
#include <cuda_runtime.h>
#include <math.h>

// Problem constants (fixed by the dataset).
#define N_MAX 50000
#define E_MAX 800000

// -------- scratch (static device globals; no runtime allocation) --------
__device__ float    g_q[N_MAX * 128];
__device__ float    g_k[N_MAX * 128];
__device__ float    g_v[N_MAX * 128];
__device__ float    g_skip[N_MAX * 128];
__device__ float    g_res[N_MAX * 128];
__device__ float    g_qe[N_MAX * 64];
__device__ float    g_s[N_MAX * 64];     // sagg
__device__ float    g_aggV[N_MAX * 128]; // unnormalized Σ ex*v
__device__ float    g_gate[N_MAX];
__device__ float    g_denom[N_MAX];
// CSR build scratch
__device__ int      g_cnt[N_MAX];
__device__ int      g_rowptr[N_MAX + 1];
__device__ int      g_wptr[N_MAX];
__device__ int2     g_srt[E_MAX];        // (src, edge_id) sorted by dst

// ---------------------------------------------------------------------------
// tf32 split: x = hi + lo, both tf32-formatted (usable directly by mma).
// ---------------------------------------------------------------------------
__device__ __forceinline__ float2 tf32_split(float xf) {
    unsigned hi;
    asm("cvt.rna.tf32.f32 %0, %1;" : "=r"(hi) : "f"(xf));
    float lo = xf - __uint_as_float(hi);
    unsigned lob;
    asm("cvt.rna.tf32.f32 %0, %1;" : "=r"(lob) : "f"(lo));
    return make_float2(__uint_as_float(hi), __uint_as_float(lob));
}

__device__ __forceinline__ void mma_tf32(float c[4], const unsigned a[4], const unsigned b[2]) {
    asm volatile(
        "mma.sync.aligned.m16n8k8.row.col.f32.tf32.tf32.f32 "
        "{%0,%1,%2,%3}, {%4,%5,%6,%7}, {%8,%9}, {%0,%1,%2,%3};"
        : "+f"(c[0]), "+f"(c[1]), "+f"(c[2]), "+f"(c[3])
        : "r"(a[0]), "r"(a[1]), "r"(a[2]), "r"(a[3]), "r"(b[0]), "r"(b[1]));
}

// ---------------------------------------------------------------------------
// Node linear via tf32x3 tensor-core MMA (5 weight sets via gridDim.y).
// ---------------------------------------------------------------------------
#define SA_STRIDE 36
#define SB_STRIDE 130
__global__ __launch_bounds__(256) void mma_linear5_kernel(
    const float* __restrict__ x,
    const float* __restrict__ Wq, const float* __restrict__ bq, float* __restrict__ oq,
    const float* __restrict__ Wk, const float* __restrict__ bk, float* __restrict__ ok,
    const float* __restrict__ Wv, const float* __restrict__ bv, float* __restrict__ ov,
    const float* __restrict__ Ws, const float* __restrict__ bs, float* __restrict__ os,
    const float* __restrict__ Wr, const float* __restrict__ br, float* __restrict__ orr,
    int n) {
    extern __shared__ float2 dyn[];
    float2* sA = dyn;                     // 64*36
    float2* sB = dyn + 64 * SA_STRIDE;    // 32*130

    const float* W; const float* b; float* out;
    switch (blockIdx.y) {
        case 0: W = Wq; b = bq; out = oq; break;
        case 1: W = Wk; b = bk; out = ok; break;
        case 2: W = Wv; b = bv; out = ov; break;
        case 3: W = Ws; b = bs; out = os; break;
        default: W = Wr; b = br; out = orr; break;
    }

    const int tid = threadIdx.x;
    const int wid = tid >> 5, lane = tid & 31;
    const int g = lane >> 2, t4 = lane & 3;
    const int wm = (wid & 1) * 32;
    const int wn = (wid >> 1) * 32;
    const int base = blockIdx.x * 64;

    float acc[2][4][4];
#pragma unroll
    for (int mi = 0; mi < 2; mi++)
#pragma unroll
        for (int ni = 0; ni < 4; ni++)
#pragma unroll
            for (int r = 0; r < 4; r++) acc[mi][ni][r] = 0.f;

    for (int kc = 0; kc < 4; kc++) {
#pragma unroll
        for (int t = 0; t < 2; t++) {
            int i = tid + t * 256;
            int row = i >> 3;
            int c4 = i & 7;
            int gr = base + row; if (gr >= n) gr = n - 1;
            const float4 xv = *(const float4*)(x + (size_t)gr * 128 + kc * 32 + c4 * 4);
            float2* dp = sA + row * SA_STRIDE + c4 * 4;
            dp[0] = tf32_split(xv.x);
            dp[1] = tf32_split(xv.y);
            dp[2] = tf32_split(xv.z);
            dp[3] = tf32_split(xv.w);
        }
#pragma unroll
        for (int t = 0; t < 4; t++) {
            int i = tid + t * 256;
            int row = i >> 5;
            int c4 = i & 31;
            const float4 wv = *(const float4*)(W + (size_t)(kc * 32 + row) * 128 + c4 * 4);
            float2* dp = sB + row * SB_STRIDE + c4 * 4;
            dp[0] = tf32_split(wv.x);
            dp[1] = tf32_split(wv.y);
            dp[2] = tf32_split(wv.z);
            dp[3] = tf32_split(wv.w);
        }
        __syncthreads();

#pragma unroll
        for (int k8 = 0; k8 < 4; k8++) {
            const int kk = k8 * 8;
            unsigned Ahi[2][4], Alo[2][4];
#pragma unroll
            for (int mi = 0; mi < 2; mi++) {
                const int r0 = wm + mi * 16 + g;
                const float2 a00 = sA[r0 * SA_STRIDE + kk + t4];
                const float2 a10 = sA[(r0 + 8) * SA_STRIDE + kk + t4];
                const float2 a01 = sA[r0 * SA_STRIDE + kk + t4 + 4];
                const float2 a11 = sA[(r0 + 8) * SA_STRIDE + kk + t4 + 4];
                Ahi[mi][0] = __float_as_uint(a00.x); Alo[mi][0] = __float_as_uint(a00.y);
                Ahi[mi][1] = __float_as_uint(a10.x); Alo[mi][1] = __float_as_uint(a10.y);
                Ahi[mi][2] = __float_as_uint(a01.x); Alo[mi][2] = __float_as_uint(a01.y);
                Ahi[mi][3] = __float_as_uint(a11.x); Alo[mi][3] = __float_as_uint(a11.y);
            }
            unsigned Bhi[4][2], Blo[4][2];
#pragma unroll
            for (int ni = 0; ni < 4; ni++) {
                const int col = wn + ni * 8 + g;
                const float2 b0 = sB[(kk + t4) * SB_STRIDE + col];
                const float2 b1 = sB[(kk + t4 + 4) * SB_STRIDE + col];
                Bhi[ni][0] = __float_as_uint(b0.x); Blo[ni][0] = __float_as_uint(b0.y);
                Bhi[ni][1] = __float_as_uint(b1.x); Blo[ni][1] = __float_as_uint(b1.y);
            }
#pragma unroll
            for (int mi = 0; mi < 2; mi++)
#pragma unroll
                for (int ni = 0; ni < 4; ni++) {
                    mma_tf32(acc[mi][ni], Ahi[mi], Bhi[ni]);
                    mma_tf32(acc[mi][ni], Ahi[mi], Blo[ni]);
                    mma_tf32(acc[mi][ni], Alo[mi], Bhi[ni]);
                }
        }
        __syncthreads();
    }

#pragma unroll
    for (int ni = 0; ni < 4; ni++) {
        const int col = wn + ni * 8 + 2 * t4;
        const float2 bb = *(const float2*)(b + col);
#pragma unroll
        for (int mi = 0; mi < 2; mi++) {
            const int node0 = base + wm + mi * 16 + g;
            if (node0 < n) {
                float2 o0 = make_float2(acc[mi][ni][0] + bb.x, acc[mi][ni][1] + bb.y);
                *(float2*)(out + (size_t)node0 * 128 + col) = o0;
            }
            const int node1 = node0 + 8;
            if (node1 < n) {
                float2 o1 = make_float2(acc[mi][ni][2] + bb.x, acc[mi][ni][3] + bb.y);
                *(float2*)(out + (size_t)node1 * 128 + col) = o1;
            }
        }
    }
}

// ---------------------------------------------------------------------------
// qe[n][d] = sum_c q[n][c] * We[d][c]   (128 -> 64)
// ---------------------------------------------------------------------------
__global__ void qe_kernel(const float* __restrict__ q, const float* __restrict__ We,
                          float* __restrict__ qe, int n) {
    __shared__ float sWeT[128 * 64];
    __shared__ float sq[16 * 128];
    const int tid = threadIdx.x;       // 128
    for (int i = tid; i < 64 * 128; i += 128) {
        int d = i >> 7, c = i & 127;
        sWeT[c * 64 + d] = We[i];
    }
    __syncthreads();
    const int cg = tid & 15;
    const int ng = tid >> 4;

    for (int base = blockIdx.x * 16; base < n; base += gridDim.x * 16) {
        const int cnt = min(16, n - base);
        __syncthreads();
        for (int i = tid; i < cnt * 128; i += 128) sq[i] = q[(size_t)base * 128 + i];
        __syncthreads();

        float acc[2][4] = {{0.f, 0.f, 0.f, 0.f}, {0.f, 0.f, 0.f, 0.f}};
#pragma unroll 2
        for (int c = 0; c < 128; c++) {
            const float4 w = *((const float4*)(sWeT + c * 64) + cg);
#pragma unroll
            for (int j = 0; j < 2; j++) {
                float xv = sq[(ng * 2 + j) * 128 + c];
                acc[j][0] = fmaf(xv, w.x, acc[j][0]);
                acc[j][1] = fmaf(xv, w.y, acc[j][1]);
                acc[j][2] = fmaf(xv, w.z, acc[j][2]);
                acc[j][3] = fmaf(xv, w.w, acc[j][3]);
            }
        }
#pragma unroll
        for (int j = 0; j < 2; j++) {
            const int node = ng * 2 + j;
            if (node < cnt) {
                float4 o = make_float4(acc[j][0], acc[j][1], acc[j][2], acc[j][3]);
                ((float4*)(qe + (size_t)(base + node) * 64))[cg] = o;
            }
        }
    }
}

// ---------------------------------------------------------------------------
// gate[n] = sigmoid(x[n] . Wg + bg)
// ---------------------------------------------------------------------------
__global__ void gate_kernel(const float* __restrict__ x, const float* __restrict__ Wg,
                            const float* __restrict__ bg, float* __restrict__ gate, int n) {
    const int node = blockIdx.x * (blockDim.x >> 5) + (threadIdx.x >> 5);
    const int lane = threadIdx.x & 31;
    if (node >= n) return;
    const float4 a = ((const float4*)(x + (size_t)node * 128))[lane];
    const float4 w = ((const float4*)Wg)[lane];
    float s = a.x * w.x + a.y * w.y + a.z * w.z + a.w * w.w;
#pragma unroll
    for (int o = 16; o > 0; o >>= 1) s += __shfl_xor_sync(0xffffffffu, s, o);
    if (lane == 0) gate[node] = 1.f / (1.f + expf(-(s + bg[0])));
}

// ---------------------------------------------------------------------------
// CSR build: zero -> histogram -> scan -> scatter
// ---------------------------------------------------------------------------
__global__ void zero_cnt_kernel(int* __restrict__ cnt, int n) {
    const int i = blockIdx.x * blockDim.x + threadIdx.x;
    if (i < n) cnt[i] = 0;
}

__global__ void hist_kernel(const int* __restrict__ dstp, int* __restrict__ cnt, int ecnt) {
    const int i = blockIdx.x * blockDim.x + threadIdx.x;
    if (i < ecnt) atomicAdd(&cnt[dstp[i]], 1);
}

#define SCAN_T 1024
__global__ void scan_kernel(const int* __restrict__ cnt, int* __restrict__ rowptr,
                            int* __restrict__ wptr, int n) {
    __shared__ int sp[SCAN_T];
    const int tid = threadIdx.x;
    const int chunk = (n + SCAN_T - 1) / SCAN_T;
    const int s = tid * chunk;
    const int e = min(s + chunk, n);
    int sum = 0;
    for (int i = s; i < e; i++) sum += cnt[i];
    sp[tid] = sum;
    __syncthreads();
    // Hillis-Steele inclusive scan
    for (int o = 1; o < SCAN_T; o <<= 1) {
        int vpr = (tid >= o) ? sp[tid - o] : 0;
        __syncthreads();
        sp[tid] += vpr;
        __syncthreads();
    }
    int run = (tid > 0) ? sp[tid - 1] : 0;
    for (int i = s; i < e; i++) {
        rowptr[i] = run;
        wptr[i] = run;
        run += cnt[i];
    }
    if (tid == SCAN_T - 1) rowptr[n] = sp[SCAN_T - 1];
}

__global__ void scatter_kernel(const int* __restrict__ ei, int* __restrict__ wptr,
                               int2* __restrict__ srt, int ecnt) {
    const int e = blockIdx.x * blockDim.x + threadIdx.x;
    if (e >= ecnt) return;
    const int dst = ei[ecnt + e];
    const int pos = atomicAdd(&wptr[dst], 1);
    srt[pos] = make_int2(ei[e], e);
}

// ---------------------------------------------------------------------------
// CSR aggregation: one warp per dst node, all accumulators in registers.
//   for edges of node: ex = exp((q[n].k[src] + qe[n].ea_e)/sqrt(128))
//   acc += ex*v[src]; sacc += ex*ea_e; den += ex. Single store per node.
// ---------------------------------------------------------------------------
__global__ __launch_bounds__(256) void agg_csr_kernel(
    const int* __restrict__ rowptr, const int2* __restrict__ srt,
    const float* __restrict__ ea, const float* __restrict__ q,
    const float* __restrict__ k, const float* __restrict__ qe,
    const float* __restrict__ v, float* __restrict__ aggV,
    float* __restrict__ sagg, float* __restrict__ denom, int n) {
    const int node = blockIdx.x * (blockDim.x >> 5) + (threadIdx.x >> 5);
    const int lane = threadIdx.x & 31;
    if (node >= n) return;
    const int beg = rowptr[node];
    const int end = rowptr[node + 1];

    const float4 qv  = ((const float4*)(q  + (size_t)node * 128))[lane];
    const float2 qev = ((const float2*)(qe + (size_t)node * 64))[lane];

    float4 acc  = make_float4(0.f, 0.f, 0.f, 0.f);
    float2 sacc = make_float2(0.f, 0.f);
    float  den  = 0.f;

#pragma unroll 2
    for (int p = beg; p < end; p++) {
        const int2 se = __ldg(&srt[p]);
        const float4 kv = ((const float4*)(k  + (size_t)se.x * 128))[lane];
        const float2 ev = ((const float2*)(ea + (size_t)se.y * 64))[lane];
        float s = qv.x * kv.x + qv.y * kv.y + qv.z * kv.z + qv.w * kv.w
                + qev.x * ev.x + qev.y * ev.y;
#pragma unroll
        for (int o = 16; o > 0; o >>= 1) s += __shfl_xor_sync(0xffffffffu, s, o);
        const float ex = expf(s * 0.08838834764831845f);   // 1/sqrt(128)
        const float4 vv = ((const float4*)(v + (size_t)se.x * 128))[lane];
        acc.x = fmaf(ex, vv.x, acc.x);
        acc.y = fmaf(ex, vv.y, acc.y);
        acc.z = fmaf(ex, vv.z, acc.z);
        acc.w = fmaf(ex, vv.w, acc.w);
        sacc.x = fmaf(ex, ev.x, sacc.x);
        sacc.y = fmaf(ex, ev.y, sacc.y);
        den += ex;
    }

    ((float4*)(aggV + (size_t)node * 128))[lane] = acc;
    ((float2*)(sagg + (size_t)node * 64))[lane]  = sacc;
    if (lane == 0) denom[node] = den;
}

// ---------------------------------------------------------------------------
// Final fused: h = (aggV + s @ We)/denom + skip ; LayerNorm ; relu ; gated res.
// ---------------------------------------------------------------------------
__global__ void final_kernel(const float* __restrict__ aggV, const float* __restrict__ sagg,
                             const float* __restrict__ We, const float* __restrict__ skip,
                             const float* __restrict__ denom,
                             const float* __restrict__ res, const float* __restrict__ gate,
                             const float* __restrict__ ln_g, const float* __restrict__ ln_b,
                             float* __restrict__ out, int n) {
    __shared__ float sWe[64 * 128];
    __shared__ float ssm[2][64];
    __shared__ float red[2][4];
    const int tid = threadIdx.x;      // 256
    for (int i = tid; i < 64 * 128; i += 256) sWe[i] = We[i];
    const int grp  = tid >> 7;
    const int c    = tid & 127;
    const int wig  = (tid & 127) >> 5;
    const int lane = tid & 31;
    const float lg = ln_g[c], lb = ln_b[c];
    __syncthreads();

    for (int base = blockIdx.x * 2; base < n; base += gridDim.x * 2) {
        const bool valid = (base + grp) < n;
        const int nn = valid ? (base + grp) : (n - 1);
        __syncthreads();
        if (c < 64) ssm[grp][c] = sagg[(size_t)nn * 64 + c];
        __syncthreads();

        float hraw = aggV[(size_t)nn * 128 + c];
#pragma unroll 4
        for (int d = 0; d < 64; d++) hraw = fmaf(ssm[grp][d], sWe[d * 128 + c], hraw);
        const float dn = denom[nn];
        const float inv = (dn > 0.f) ? (1.f / dn) : 0.f;
        float h = hraw * inv + skip[(size_t)nn * 128 + c];

        float t = h;
#pragma unroll
        for (int o = 16; o > 0; o >>= 1) t += __shfl_xor_sync(0xffffffffu, t, o);
        if (lane == 0) red[grp][wig] = t;
        __syncthreads();
        const float mu = (red[grp][0] + red[grp][1] + red[grp][2] + red[grp][3]) * (1.f / 128.f);
        __syncthreads();

        const float dv = h - mu;
        t = dv * dv;
#pragma unroll
        for (int o = 16; o > 0; o >>= 1) t += __shfl_xor_sync(0xffffffffu, t, o);
        if (lane == 0) red[grp][wig] = t;
        __syncthreads();
        const float var = (red[grp][0] + red[grp][1] + red[grp][2] + red[grp][3]) * (1.f / 128.f);

        float y = dv * rsqrtf(var + 1e-5f) * lg + lb;
        y = fmaxf(y, 0.f);
        const float g = gate[nn];
        const float ov = g * y + (1.f - g) * res[(size_t)nn * 128 + c];
        if (valid) out[(size_t)(base + grp) * 128 + c] = ov;
    }
}

// ---------------------------------------------------------------------------
extern "C" void kernel_launch(void* const* d_in, const int* in_sizes, int n_in,
                              void* d_out, int out_size) {
    const float* x     = (const float*)d_in[0];
    const int*   ei    = (const int*)  d_in[1];
    const float* ea    = (const float*)d_in[2];
    const float* Wq    = (const float*)d_in[3];
    const float* bq    = (const float*)d_in[4];
    const float* Wk    = (const float*)d_in[5];
    const float* bk    = (const float*)d_in[6];
    const float* Wv    = (const float*)d_in[7];
    const float* bv    = (const float*)d_in[8];
    const float* We    = (const float*)d_in[9];
    const float* Wskip = (const float*)d_in[10];
    const float* bskip = (const float*)d_in[11];
    const float* ln_g  = (const float*)d_in[12];
    const float* ln_b  = (const float*)d_in[13];
    const float* Wres  = (const float*)d_in[14];
    const float* bres  = (const float*)d_in[15];
    const float* Wgate = (const float*)d_in[16];
    const float* bgate = (const float*)d_in[17];
    float* out = (float*)d_out;

    int n = in_sizes[0] / 128;
    int ecnt = in_sizes[1] / 2;
    if (n > N_MAX) n = N_MAX;
    if (ecnt > E_MAX) ecnt = E_MAX;

    float *q, *k, *v, *skip, *res, *qe, *sagg, *aggV, *gate, *denom;
    int *cnt, *rowptr, *wptr;
    int2 *srt;
    cudaGetSymbolAddress((void**)&q,      g_q);
    cudaGetSymbolAddress((void**)&k,      g_k);
    cudaGetSymbolAddress((void**)&v,      g_v);
    cudaGetSymbolAddress((void**)&skip,   g_skip);
    cudaGetSymbolAddress((void**)&res,    g_res);
    cudaGetSymbolAddress((void**)&qe,     g_qe);
    cudaGetSymbolAddress((void**)&sagg,   g_s);
    cudaGetSymbolAddress((void**)&aggV,   g_aggV);
    cudaGetSymbolAddress((void**)&gate,   g_gate);
    cudaGetSymbolAddress((void**)&denom,  g_denom);
    cudaGetSymbolAddress((void**)&cnt,    g_cnt);
    cudaGetSymbolAddress((void**)&rowptr, g_rowptr);
    cudaGetSymbolAddress((void**)&wptr,   g_wptr);
    cudaGetSymbolAddress((void**)&srt,    g_srt);

    const int mma_smem = (64 * SA_STRIDE + 32 * SB_STRIDE) * (int)sizeof(float2);
    cudaFuncSetAttribute(mma_linear5_kernel, cudaFuncAttributeMaxDynamicSharedMemorySize, mma_smem);

    // CSR build (independent of projections; launch first to overlap nothing but be ready)
    zero_cnt_kernel<<<(n + 255) / 256, 256>>>(cnt, n);
    hist_kernel<<<(ecnt + 255) / 256, 256>>>(ei + ecnt, cnt, ecnt);
    scan_kernel<<<1, SCAN_T>>>(cnt, rowptr, wptr, n);
    scatter_kernel<<<(ecnt + 255) / 256, 256>>>(ei, wptr, srt, ecnt);

    // Node projections (all 5 in one launch; gridDim.y selects weight set)
    dim3 mma_grid((n + 63) / 64, 5, 1);
    mma_linear5_kernel<<<mma_grid, 256, mma_smem>>>(
        x, Wq, bq, q, Wk, bk, k, Wv, bv, v, Wskip, bskip, skip, Wres, bres, res, n);

    qe_kernel<<<740, 128>>>(q, We, qe, n);
    gate_kernel<<<(n + 7) / 8, 256>>>(x, Wgate, bgate, gate, n);

    // Atomic-free CSR aggregation: one warp per dst node
    agg_csr_kernel<<<(n + 7) / 8, 256>>>(rowptr, srt, ea, q, k, qe, v,
                                         aggV, sagg, denom, n);

    // Final fused epilogue
    final_kernel<<<740, 256>>>(aggV, sagg, We, skip, denom, res, gate, ln_g, ln_b, out, n);
}